// round 15
// baseline (speedup 1.0000x reference)
#include <cuda_runtime.h>
#include <cuda_fp16.h>
#include <cstdint>

#define QKV_SZ (512u * 8u * 64u * 64u)   // halfs per matrix
__device__ __align__(16) __half g_qkv[3 * QKV_SZ];   // fp16 [which][bw][h][t][d]
__device__ __align__(16) __half g_xh[32768u * 512u]; // x as fp16
__device__ __align__(16) __half g_wh[1536u * 512u];  // Wq|Wk|Wv as fp16
__device__ int g_cnt[512];                           // per-window proj completion (target 12)

__device__ __forceinline__ uint32_t pack2(float a, float b) {
    __half2 h = __halves2half2(__float2half_rn(a), __float2half_rn(b));
    return *(uint32_t*)&h;
}

__device__ __forceinline__ void mma_f16(float c[4], const uint32_t a[4],
                                        uint32_t b0, uint32_t b1) {
    asm volatile(
        "mma.sync.aligned.m16n8k16.row.col.f32.f16.f16.f32 "
        "{%0,%1,%2,%3}, {%4,%5,%6,%7}, {%8,%9}, {%0,%1,%2,%3};"
        : "+f"(c[0]), "+f"(c[1]), "+f"(c[2]), "+f"(c[3])
        : "r"(a[0]), "r"(a[1]), "r"(a[2]), "r"(a[3]), "r"(b0), "r"(b1));
}

__device__ __forceinline__ void ldm_x4(uint32_t* r, uint32_t addr) {
    asm volatile("ldmatrix.sync.aligned.m8n8.x4.shared.b16 {%0,%1,%2,%3}, [%4];"
                 : "=r"(r[0]), "=r"(r[1]), "=r"(r[2]), "=r"(r[3]) : "r"(addr));
}
__device__ __forceinline__ void ldm_x4_trans(uint32_t* r, uint32_t addr) {
    asm volatile("ldmatrix.sync.aligned.m8n8.x4.trans.shared.b16 {%0,%1,%2,%3}, [%4];"
                 : "=r"(r[0]), "=r"(r[1]), "=r"(r[2]), "=r"(r[3]) : "r"(addr));
}

__device__ __forceinline__ void cp_async16(uint32_t smem_addr, const void* gptr) {
    asm volatile("cp.async.cg.shared.global [%0], [%1], 16;\n" :: "r"(smem_addr), "l"(gptr));
}
__device__ __forceinline__ void cp_commit() { asm volatile("cp.async.commit_group;"); }
template <int N> __device__ __forceinline__ void cp_wait() {
    asm volatile("cp.async.wait_group %0;" :: "n"(N));
}

// ---------------------------------------------------------------------------
// Zero the window counters (every launch / graph replay).
// ---------------------------------------------------------------------------
__global__ void zero_cnt_kernel()
{
    g_cnt[blockIdx.x * 256 + threadIdx.x] = 0;
}

// ---------------------------------------------------------------------------
// Pre-convert: fp32 -> fp16(RN). 8 floats per thread.
// ---------------------------------------------------------------------------
__global__ void __launch_bounds__(256) conv_x_kernel(const float* __restrict__ x)
{
    const int i = blockIdx.x * 256 + threadIdx.x;
    float4 v0 = ((const float4*)x)[2 * i];
    float4 v1 = ((const float4*)x)[2 * i + 1];
    uint4 u;
    u.x = pack2(v0.x, v0.y); u.y = pack2(v0.z, v0.w);
    u.z = pack2(v1.x, v1.y); u.w = pack2(v1.z, v1.w);
    ((uint4*)g_xh)[i] = u;
}

__global__ void __launch_bounds__(256) conv_w_kernel(
    const float* __restrict__ Wq, const float* __restrict__ Wk, const float* __restrict__ Wv)
{
    const int i = blockIdx.x * 256 + threadIdx.x;
    const int which = i >> 15;
    const int sub = i & 32767;
    const float* W = (which == 0) ? Wq : (which == 1) ? Wk : Wv;
    float4 v0 = ((const float4*)W)[2 * sub];
    float4 v1 = ((const float4*)W)[2 * sub + 1];
    uint4 u;
    u.x = pack2(v0.x, v0.y); u.y = pack2(v0.z, v0.w);
    u.z = pack2(v1.x, v1.y); u.w = pack2(v1.z, v1.w);
    ((uint4*)g_wh)[i] = u;
}

// ---------------------------------------------------------------------------
// Fused kernel. Grid (12, 256), 256 threads, 2 CTAs/SM.
// Phase 1 (all CTAs): proj tile 128x128 (R14 code). nb = bx*128, mb = y*128.
//   After epilogue: fence + counter increment for windows 2y, 2y+1.
// Phase 2 (bx in [4,12)): attention job (window 2y + ((bx-4)>>2),
//   head pair (bx-4)&3), 2 heads x 4 warps, reusing stage smem.
//   Spin on g_cnt[w]==12. Job bids are within +7 of the last producer bid ->
//   deadlock-free under in-order CTA distribution.
// ---------------------------------------------------------------------------
#define KC 32
#define PW 20                            // words per staged row (16 data + 4 pad)
#define STAGE_W (256 * PW)               // 128 A rows + 128 B rows = 5120 words
#define NSTAGE 4
#define PROJ_SMEM (NSTAGE * STAGE_W * 4) // 81920 B -> 2 CTAs/SM
#define APITCH 36                        // attn row pitch (words)

__global__ void __launch_bounds__(256, 2) fused_kernel(
    const float* __restrict__ bq, const float* __restrict__ bk, const float* __restrict__ bv,
    const float* __restrict__ Bbias, float* __restrict__ out)
{
    extern __shared__ uint32_t sm[];

    const int tid  = threadIdx.x;
    const int warp = tid >> 5, lane = tid & 31;
    const int g = lane >> 2, tig = lane & 3;
    const int l8 = lane >> 3, r8 = lane & 7;

    const int bx = blockIdx.x, by = blockIdx.y;
    const int nb = bx * 128;
    const int mb = by * 128;
    const int which = nb >> 9;
    const int nw0 = nb & 511;
    const float* __restrict__ bias = (which == 0) ? bq : (which == 1) ? bk : bv;
    __half* __restrict__ dst = g_qkv + (size_t)which * QKV_SZ;

    const uint32_t smem_base = (uint32_t)__cvta_generic_to_shared(sm);

    // ======================= Phase 1: projection =======================
    {
        const int wm = (warp >> 2) * 64;
        const int wn = (warp & 3) * 32;
        const uint32_t a_off = (uint32_t)((wm + (l8 & 1) * 8 + r8) * PW + (l8 >> 1) * 4);
        const uint32_t b_off = (uint32_t)((128 + wn + (l8 >> 1) * 8 + r8) * PW + (l8 & 1) * 4);

        float acc[4][4][4];
#pragma unroll
        for (int i = 0; i < 4; i++)
#pragma unroll
            for (int j = 0; j < 4; j++)
#pragma unroll
                for (int c = 0; c < 4; c++) acc[i][j][c] = 0.f;

        auto issue = [&](int c) {
            const uint32_t sbase = smem_base + (uint32_t)((c & 3) * STAGE_W) * 4u;
            const int kel = c * KC;
#pragma unroll
            for (int q = 0; q < 4; q++) {
                const int idx = q * 256 + tid;
                if (idx < 512) {             // A
                    const int row = idx >> 2, i = idx & 3;
                    cp_async16(sbase + (uint32_t)(row * PW + i * 4) * 4u,
                               g_xh + (size_t)(mb + row) * 512 + kel + i * 8);
                } else {                     // B
                    const int bidx = idx - 512;
                    const int row = bidx >> 2, i = bidx & 3;
                    cp_async16(sbase + (uint32_t)((128 + row) * PW + i * 4) * 4u,
                               g_wh + (size_t)(nb + row) * 512 + kel + i * 8);
                }
            }
            cp_commit();
        };

        issue(0); issue(1); issue(2);

        for (int c = 0; c < 16; c++) {
            if (c <= 13) cp_wait<2>();
            else if (c == 14) cp_wait<1>();
            else cp_wait<0>();
            __syncthreads();
            if (c + 3 < 16) issue(c + 3);

            const uint32_t stage_addr = smem_base + (uint32_t)((c & 3) * STAGE_W) * 4u;

#pragma unroll
            for (int step = 0; step < 2; step++) {
                const uint32_t so = stage_addr + (uint32_t)(step * 8) * 4u;
                uint32_t a[4][4], b[2][4];
#pragma unroll
                for (int i = 0; i < 4; i++)
                    ldm_x4(a[i], so + (a_off + (uint32_t)(i * 16 * PW)) * 4u);
#pragma unroll
                for (int jj = 0; jj < 2; jj++)
                    ldm_x4(b[jj], so + (b_off + (uint32_t)(jj * 16 * PW)) * 4u);
#pragma unroll
                for (int jj = 0; jj < 2; jj++)
#pragma unroll
                    for (int i = 0; i < 4; i++) {
                        mma_f16(acc[i][2 * jj    ], a[i], b[jj][0], b[jj][1]);
                        mma_f16(acc[i][2 * jj + 1], a[i], b[jj][2], b[jj][3]);
                    }
            }
        }

        // Epilogue: +bias fp32, pack half2, scatter [bw][h][t][d].
#pragma unroll
        for (int i = 0; i < 4; i++) {
            const int m0 = mb + (warp >> 2) * 64 + i * 16 + g;
#pragma unroll
            for (int j = 0; j < 4; j++) {
                const int col = nw0 + (warp & 3) * 32 + j * 8 + tig * 2;
                const float bv0 = bias[col], bv1 = bias[col + 1];
                const int h = col >> 6, d = col & 63;
                {
                    const int m = m0;
                    size_t o = (((size_t)(m >> 6) * 8 + h) * 64 + (m & 63)) * 64 + d;
                    *(uint32_t*)&dst[o] = pack2(acc[i][j][0] + bv0, acc[i][j][1] + bv1);
                }
                {
                    const int m = m0 + 8;
                    size_t o = (((size_t)(m >> 6) * 8 + h) * 64 + (m & 63)) * 64 + d;
                    *(uint32_t*)&dst[o] = pack2(acc[i][j][2] + bv0, acc[i][j][3] + bv1);
                }
            }
        }
    }

    // ---- publish: this CTA finished its N-slice for windows 2y, 2y+1 ----
    __threadfence();
    __syncthreads();
    if (tid == 0) {
        atomicAdd(&g_cnt[2 * by], 1);
        atomicAdd(&g_cnt[2 * by + 1], 1);
    }

    if (bx < 4) return;                 // Q-tile CTAs carry no attention job

    // ======================= Phase 2: attention =======================
    const int jb = bx - 4;              // 0..7
    const int bw = 2 * by + (jb >> 2);  // this job's window
    const int hp = jb & 3;              // head pair

    if (tid == 0) {
        while (atomicAdd(&g_cnt[bw], 0) < 12) __nanosleep(200);
    }
    __syncthreads();
    __threadfence();

    // smem layout (words): qp[2][2304], k[2][2304], v[2][2304]
    const int s  = warp >> 2;           // head slot (0/1)
    const int h  = hp * 2 + s;
    const int qr = (warp & 3) * 16;

    const uint32_t qp_w0 = 0, k_w0 = 4608, v_w0 = 9216;
    const uint32_t qp_base = smem_base + (qp_w0 + (uint32_t)s * 2304) * 4u;
    const uint32_t k_base  = smem_base + (k_w0  + (uint32_t)s * 2304) * 4u;
    const uint32_t v_base  = smem_base + (v_w0  + (uint32_t)s * 2304) * 4u;
    uint32_t* qp_arr = sm + qp_w0 + s * 2304;

    // Loads: per head slot ss, 512 chunks x 16B per tensor; 2/thread each.
#pragma unroll
    for (int ss = 0; ss < 2; ss++) {
        const size_t hb = ((size_t)bw * 8 + hp * 2 + ss) * 4096;
        const __half* qg = g_qkv + hb;
        const __half* kg = g_qkv + QKV_SZ + hb;
        const __half* vg = g_qkv + 2u * QKV_SZ + hb;
        const uint32_t sq = smem_base + (qp_w0 + (uint32_t)ss * 2304) * 4u;
        const uint32_t sk = smem_base + (k_w0  + (uint32_t)ss * 2304) * 4u;
        const uint32_t sv = smem_base + (v_w0  + (uint32_t)ss * 2304) * 4u;
#pragma unroll
        for (int i = 0; i < 2; i++) {
            const int c = i * 256 + tid;
            const int t = c >> 3, w4 = (c & 7) * 4;
            const uint32_t soff = (uint32_t)(t * APITCH + w4) * 4u;
            cp_async16(sq + soff, qg + c * 8);
            cp_async16(sk + soff, kg + c * 8);
            cp_async16(sv + soff, vg + c * 8);
        }
    }
    cp_commit();
    cp_wait<0>();
    __syncthreads();

    const uint32_t aq_off = (uint32_t)((qr + (l8 & 1) * 8 + r8) * APITCH + (l8 >> 1) * 4);
    const uint32_t bk_off = (uint32_t)(((l8 >> 1) * 8 + r8) * APITCH + (l8 & 1) * 4);
    const uint32_t bv_off = (uint32_t)(((l8 & 1) * 8 + r8) * APITCH + (l8 >> 1) * 4);

    // ---- S = Q K^T ----
    float sc[8][4];
#pragma unroll
    for (int j = 0; j < 8; j++)
#pragma unroll
        for (int c = 0; c < 4; c++) sc[j][c] = 0.f;

#pragma unroll
    for (int kk = 0; kk < 4; kk++) {
        uint32_t a[4];
        ldm_x4(a, qp_base + (aq_off + (uint32_t)(kk * 8)) * 4u);
#pragma unroll
        for (int jj = 0; jj < 4; jj++) {
            uint32_t b[4];
            ldm_x4(b, k_base + (bk_off + (uint32_t)(jj * 16 * APITCH + kk * 8)) * 4u);
            mma_f16(sc[2 * jj    ], a, b[0], b[1]);
            mma_f16(sc[2 * jj + 1], a, b[2], b[3]);
        }
    }

    // ---- scale + bias + softmax ----
    const float scale = 0.125f;
    float mx0 = -1e30f, mx1 = -1e30f;
#pragma unroll
    for (int j = 0; j < 8; j++) {
        float2 b0 = *(const float2*)&Bbias[(qr + g    ) * 64 + j * 8 + tig * 2];
        float2 b1 = *(const float2*)&Bbias[(qr + g + 8) * 64 + j * 8 + tig * 2];
        sc[j][0] = sc[j][0] * scale + b0.x;
        sc[j][1] = sc[j][1] * scale + b0.y;
        sc[j][2] = sc[j][2] * scale + b1.x;
        sc[j][3] = sc[j][3] * scale + b1.y;
        mx0 = fmaxf(mx0, fmaxf(sc[j][0], sc[j][1]));
        mx1 = fmaxf(mx1, fmaxf(sc[j][2], sc[j][3]));
    }
    mx0 = fmaxf(mx0, __shfl_xor_sync(0xffffffffu, mx0, 1));
    mx0 = fmaxf(mx0, __shfl_xor_sync(0xffffffffu, mx0, 2));
    mx1 = fmaxf(mx1, __shfl_xor_sync(0xffffffffu, mx1, 1));
    mx1 = fmaxf(mx1, __shfl_xor_sync(0xffffffffu, mx1, 2));

    float sum0 = 0.f, sum1 = 0.f;
#pragma unroll
    for (int j = 0; j < 8; j++) {
        sc[j][0] = __expf(sc[j][0] - mx0);
        sc[j][1] = __expf(sc[j][1] - mx0);
        sc[j][2] = __expf(sc[j][2] - mx1);
        sc[j][3] = __expf(sc[j][3] - mx1);
        sum0 += sc[j][0] + sc[j][1];
        sum1 += sc[j][2] + sc[j][3];
    }
    sum0 += __shfl_xor_sync(0xffffffffu, sum0, 1);
    sum0 += __shfl_xor_sync(0xffffffffu, sum0, 2);
    sum1 += __shfl_xor_sync(0xffffffffu, sum1, 1);
    sum1 += __shfl_xor_sync(0xffffffffu, sum1, 2);
    const float inv0 = 1.0f / sum0, inv1 = 1.0f / sum1;

    // ---- P (fp16) over Q smem (warp-private rows) ----
    __syncwarp();
#pragma unroll
    for (int j = 0; j < 8; j++) {
        qp_arr[(qr + g    ) * APITCH + j * 4 + tig] = pack2(sc[j][0] * inv0, sc[j][1] * inv0);
        qp_arr[(qr + g + 8) * APITCH + j * 4 + tig] = pack2(sc[j][2] * inv1, sc[j][3] * inv1);
    }
    __syncwarp();

    // ---- O = P V ----
    float o[8][4];
#pragma unroll
    for (int j = 0; j < 8; j++)
#pragma unroll
        for (int c = 0; c < 4; c++) o[j][c] = 0.f;

#pragma unroll
    for (int kk = 0; kk < 4; kk++) {
        uint32_t a[4];
        ldm_x4(a, qp_base + (aq_off + (uint32_t)(kk * 8)) * 4u);
#pragma unroll
        for (int jj = 0; jj < 4; jj++) {
            uint32_t b[4];
            ldm_x4_trans(b, v_base + (bv_off + (uint32_t)(kk * 16 * APITCH + jj * 8)) * 4u);
            mma_f16(o[2 * jj    ], a, b[0], b[1]);
            mma_f16(o[2 * jj + 1], a, b[2], b[3]);
        }
    }

    // ---- output: flat[((bw*64 + t) * 512) + h*64 + d], fp32 ----
    float* o0 = out + ((size_t)bw * 64 + qr + g) * 512 + h * 64;
    float* o1 = o0 + 8 * 512;
#pragma unroll
    for (int j = 0; j < 8; j++) {
        *(float2*)&o0[j * 8 + tig * 2] = make_float2(o[j][0], o[j][1]);
        *(float2*)&o1[j * 8 + tig * 2] = make_float2(o[j][2], o[j][3]);
    }
}

// ---------------------------------------------------------------------------
extern "C" void kernel_launch(void* const* d_in, const int* in_sizes, int n_in,
                              void* d_out, int out_size)
{
    const float* x  = (const float*)d_in[0];
    const float* Wq = (const float*)d_in[1];
    const float* bq = (const float*)d_in[2];
    const float* Wk = (const float*)d_in[3];
    const float* bk = (const float*)d_in[4];
    const float* Wv = (const float*)d_in[5];
    const float* bv = (const float*)d_in[6];
    const float* Bb = (const float*)d_in[7];
    float* out = (float*)d_out;

    cudaFuncSetAttribute(fused_kernel, cudaFuncAttributeMaxDynamicSharedMemorySize,
                         PROJ_SMEM);

    zero_cnt_kernel<<<2, 256>>>();
    conv_x_kernel<<<8192, 256>>>(x);
    conv_w_kernel<<<384, 256>>>(Wq, Wk, Wv);

    dim3 gA(12, 256);
    fused_kernel<<<gA, 256, PROJ_SMEM>>>(bq, bk, bv, Bb, out);
}

// round 16
// speedup vs baseline: 1.1333x; 1.1333x over previous
#include <cuda_runtime.h>
#include <cuda_fp16.h>
#include <cstdint>

#define QKV_SZ (512u * 8u * 64u * 64u)   // halfs per matrix
__device__ __align__(16) __half g_qkv[3 * QKV_SZ];   // fp16 [which][bw][h][t][d]
__device__ __align__(16) __half g_xh[32768u * 512u]; // x as fp16
__device__ __align__(16) __half g_wh[1536u * 512u];  // Wq|Wk|Wv as fp16

__device__ __forceinline__ uint32_t pack2(float a, float b) {
    __half2 h = __halves2half2(__float2half_rn(a), __float2half_rn(b));
    return *(uint32_t*)&h;
}

__device__ __forceinline__ void mma_f16(float c[4], const uint32_t a[4],
                                        uint32_t b0, uint32_t b1) {
    asm volatile(
        "mma.sync.aligned.m16n8k16.row.col.f32.f16.f16.f32 "
        "{%0,%1,%2,%3}, {%4,%5,%6,%7}, {%8,%9}, {%0,%1,%2,%3};"
        : "+f"(c[0]), "+f"(c[1]), "+f"(c[2]), "+f"(c[3])
        : "r"(a[0]), "r"(a[1]), "r"(a[2]), "r"(a[3]), "r"(b0), "r"(b1));
}

__device__ __forceinline__ void ldm_x4(uint32_t* r, uint32_t addr) {
    asm volatile("ldmatrix.sync.aligned.m8n8.x4.shared.b16 {%0,%1,%2,%3}, [%4];"
                 : "=r"(r[0]), "=r"(r[1]), "=r"(r[2]), "=r"(r[3]) : "r"(addr));
}
__device__ __forceinline__ void ldm_x4_trans(uint32_t* r, uint32_t addr) {
    asm volatile("ldmatrix.sync.aligned.m8n8.x4.trans.shared.b16 {%0,%1,%2,%3}, [%4];"
                 : "=r"(r[0]), "=r"(r[1]), "=r"(r[2]), "=r"(r[3]) : "r"(addr));
}

__device__ __forceinline__ void cp_async16(uint32_t smem_addr, const void* gptr) {
    asm volatile("cp.async.cg.shared.global [%0], [%1], 16;\n" :: "r"(smem_addr), "l"(gptr));
}
__device__ __forceinline__ void cp_commit() { asm volatile("cp.async.commit_group;"); }
template <int N> __device__ __forceinline__ void cp_wait() {
    asm volatile("cp.async.wait_group %0;" :: "n"(N));
}

// ---------------------------------------------------------------------------
// Pre-convert: fp32 -> fp16(RN). 8 floats per thread.
// ---------------------------------------------------------------------------
__global__ void __launch_bounds__(256) conv_x_kernel(const float* __restrict__ x)
{
    const int i = blockIdx.x * 256 + threadIdx.x;
    float4 v0 = ((const float4*)x)[2 * i];
    float4 v1 = ((const float4*)x)[2 * i + 1];
    uint4 u;
    u.x = pack2(v0.x, v0.y); u.y = pack2(v0.z, v0.w);
    u.z = pack2(v1.x, v1.y); u.w = pack2(v1.z, v1.w);
    ((uint4*)g_xh)[i] = u;
}

__global__ void __launch_bounds__(256) conv_w_kernel(
    const float* __restrict__ Wq, const float* __restrict__ Wk, const float* __restrict__ Wv)
{
    const int i = blockIdx.x * 256 + threadIdx.x;
    const int which = i >> 15;
    const int sub = i & 32767;
    const float* W = (which == 0) ? Wq : (which == 1) ? Wk : Wv;
    float4 v0 = ((const float4*)W)[2 * sub];
    float4 v1 = ((const float4*)W)[2 * sub + 1];
    uint4 u;
    u.x = pack2(v0.x, v0.y); u.y = pack2(v0.z, v0.w);
    u.z = pack2(v1.x, v1.y); u.w = pack2(v1.z, v1.w);
    ((uint4*)g_wh)[i] = u;
}

// ---------------------------------------------------------------------------
// Kernel A: QKV projection, fp16 m16n8k16, 2 CTAs/SM.
// CTA tile 128x128, 256 threads, 8 warps (2x4 grid of 64x32 warp tiles).
// K chunk 64 (4 k16-steps between barriers -> ldm/mma interleave room),
// 3-stage cp.async pipeline (prefetch distance 2). 36 KB/stage, 108 KB total.
// Grid (12, 256): blockIdx.x = N-tile (fast) -> x L2 reuse.
// ---------------------------------------------------------------------------
#define KC 64
#define PW 36                            // words per staged row (32 data + 4 pad)
#define STAGE_W (256 * PW)               // 128 A rows + 128 B rows = 9216 words
#define NSTAGE 3
#define PROJ_SMEM (NSTAGE * STAGE_W * 4) // 110592 B -> 2 CTAs/SM

__global__ void __launch_bounds__(256, 2) qkv_proj_kernel(
    const float* __restrict__ bq, const float* __restrict__ bk, const float* __restrict__ bv)
{
    extern __shared__ uint32_t sm[];

    const int tid  = threadIdx.x;
    const int warp = tid >> 5, lane = tid & 31;
    const int g = lane >> 2, tig = lane & 3;
    const int l8 = lane >> 3, r8 = lane & 7;
    const int wm = (warp >> 2) * 64;     // 2 row-groups
    const int wn = (warp & 3) * 32;      // 4 col-groups

    const int nb = blockIdx.x * 128;
    const int mb = blockIdx.y * 128;
    const int which = nb >> 9;
    const int nw0 = nb & 511;
    const float* __restrict__ bias = (which == 0) ? bq : (which == 1) ? bk : bv;
    __half* __restrict__ dst = g_qkv + (size_t)which * QKV_SZ;

    const uint32_t smem_base = (uint32_t)__cvta_generic_to_shared(sm);

    const uint32_t a_off = (uint32_t)((wm + (l8 & 1) * 8 + r8) * PW + (l8 >> 1) * 4);
    const uint32_t b_off = (uint32_t)((128 + wn + (l8 >> 1) * 8 + r8) * PW + (l8 & 1) * 4);

    float acc[4][4][4];
#pragma unroll
    for (int i = 0; i < 4; i++)
#pragma unroll
        for (int j = 0; j < 4; j++)
#pragma unroll
            for (int c = 0; c < 4; c++) acc[i][j][c] = 0.f;

    // Per stage: (128 A + 128 B) rows x 8 x 16B = 2048 cp ops, 8/thread.
    auto issue = [&](int c) {
        const uint32_t sbase = smem_base + (uint32_t)((c % NSTAGE) * STAGE_W) * 4u;
        const int kel = c * KC;
#pragma unroll
        for (int q = 0; q < 8; q++) {
            const int idx = q * 256 + tid;
            if (idx < 1024) {            // A
                const int row = idx >> 3, seg = idx & 7;
                cp_async16(sbase + (uint32_t)(row * PW + seg * 4) * 4u,
                           g_xh + (size_t)(mb + row) * 512 + kel + seg * 8);
            } else {                     // B
                const int bidx = idx - 1024;
                const int row = bidx >> 3, seg = bidx & 7;
                cp_async16(sbase + (uint32_t)((128 + row) * PW + seg * 4) * 4u,
                           g_wh + (size_t)(nb + row) * 512 + kel + seg * 8);
            }
        }
        cp_commit();
    };

    issue(0); issue(1);

    for (int c = 0; c < 8; c++) {
        if (c < 7) cp_wait<1>(); else cp_wait<0>();
        __syncthreads();
        if (c + 2 < 8) issue(c + 2);

        const uint32_t stage_addr = smem_base + (uint32_t)((c % NSTAGE) * STAGE_W) * 4u;

#pragma unroll
        for (int step = 0; step < 4; step++) {   // 4 k16-steps per chunk
            const uint32_t so = stage_addr + (uint32_t)(step * 8) * 4u;
            uint32_t a[4][4], b[2][4];
#pragma unroll
            for (int i = 0; i < 4; i++)
                ldm_x4(a[i], so + (a_off + (uint32_t)(i * 16 * PW)) * 4u);
#pragma unroll
            for (int jj = 0; jj < 2; jj++)
                ldm_x4(b[jj], so + (b_off + (uint32_t)(jj * 16 * PW)) * 4u);
#pragma unroll
            for (int jj = 0; jj < 2; jj++)
#pragma unroll
                for (int i = 0; i < 4; i++) {
                    mma_f16(acc[i][2 * jj    ], a[i], b[jj][0], b[jj][1]);
                    mma_f16(acc[i][2 * jj + 1], a[i], b[jj][2], b[jj][3]);
                }
        }
    }

    // Epilogue: +bias fp32, pack half2, scatter [bw][h][t][d].
#pragma unroll
    for (int i = 0; i < 4; i++) {
        const int m0 = mb + wm + i * 16 + g;
#pragma unroll
        for (int j = 0; j < 4; j++) {
            const int col = nw0 + wn + j * 8 + tig * 2;
            const float bv0 = bias[col], bv1 = bias[col + 1];
            const int h = col >> 6, d = col & 63;
            {
                const int m = m0;
                size_t o = (((size_t)(m >> 6) * 8 + h) * 64 + (m & 63)) * 64 + d;
                *(uint32_t*)&dst[o] = pack2(acc[i][j][0] + bv0, acc[i][j][1] + bv1);
            }
            {
                const int m = m0 + 8;
                size_t o = (((size_t)(m >> 6) * 8 + h) * 64 + (m & 63)) * 64 + d;
                *(uint32_t*)&dst[o] = pack2(acc[i][j][2] + bv0, acc[i][j][3] + bv1);
            }
        }
    }
}

// ---------------------------------------------------------------------------
// Kernel B: per-(window, head) attention, fp16 mma + ldmatrix.x4.
// 4096 CTAs x 128 threads. Q/K/V via cp.async (12 x 16B in flight / thread).
// ---------------------------------------------------------------------------
#define APITCH 36

__global__ void __launch_bounds__(128) attn_kernel(
    const float* __restrict__ Bbias, float* __restrict__ out)
{
    __shared__ uint32_t qp_s[64 * APITCH];   // Q, later P (warp-private rows)
    __shared__ uint32_t k_s [64 * APITCH];
    __shared__ uint32_t v_s [64 * APITCH];   // [t][d] row-major

    const int tid  = threadIdx.x;
    const int warp = tid >> 5, lane = tid & 31;
    const int g = lane >> 2, tig = lane & 3;
    const int l8 = lane >> 3, r8 = lane & 7;
    const int wh = blockIdx.x;
    const int h  = wh & 7;
    const int bw = wh >> 3;
    const size_t base = (size_t)wh * 4096;

    const __half* qg = g_qkv + base;
    const __half* kg = g_qkv + QKV_SZ + base;
    const __half* vg = g_qkv + 2u * QKV_SZ + base;

    const uint32_t qp_base = (uint32_t)__cvta_generic_to_shared(qp_s);
    const uint32_t k_base  = (uint32_t)__cvta_generic_to_shared(k_s);
    const uint32_t v_base  = (uint32_t)__cvta_generic_to_shared(v_s);

#pragma unroll
    for (int i = 0; i < 4; i++) {
        const int c = i * 128 + tid;
        const int t = c >> 3, w4 = (c & 7) * 4;
        const uint32_t soff = (uint32_t)(t * APITCH + w4) * 4u;
        cp_async16(qp_base + soff, qg + c * 8);
        cp_async16(k_base  + soff, kg + c * 8);
        cp_async16(v_base  + soff, vg + c * 8);
    }
    cp_commit();
    cp_wait<0>();
    __syncthreads();

    const int qr = warp * 16;

    const uint32_t aq_off = (uint32_t)((qr + (l8 & 1) * 8 + r8) * APITCH + (l8 >> 1) * 4);
    const uint32_t bk_off = (uint32_t)(((l8 >> 1) * 8 + r8) * APITCH + (l8 & 1) * 4);
    const uint32_t bv_off = (uint32_t)(((l8 & 1) * 8 + r8) * APITCH + (l8 >> 1) * 4);

    // ---- S = Q K^T ----
    float s[8][4];
#pragma unroll
    for (int j = 0; j < 8; j++)
#pragma unroll
        for (int c = 0; c < 4; c++) s[j][c] = 0.f;

#pragma unroll
    for (int kk = 0; kk < 4; kk++) {
        uint32_t a[4];
        ldm_x4(a, qp_base + (aq_off + (uint32_t)(kk * 8)) * 4u);
#pragma unroll
        for (int jj = 0; jj < 4; jj++) {
            uint32_t b[4];
            ldm_x4(b, k_base + (bk_off + (uint32_t)(jj * 16 * APITCH + kk * 8)) * 4u);
            mma_f16(s[2 * jj    ], a, b[0], b[1]);
            mma_f16(s[2 * jj + 1], a, b[2], b[3]);
        }
    }

    // ---- scale + bias + softmax ----
    const float scale = 0.125f;
    float mx0 = -1e30f, mx1 = -1e30f;
#pragma unroll
    for (int j = 0; j < 8; j++) {
        float2 b0 = *(const float2*)&Bbias[(qr + g    ) * 64 + j * 8 + tig * 2];
        float2 b1 = *(const float2*)&Bbias[(qr + g + 8) * 64 + j * 8 + tig * 2];
        s[j][0] = s[j][0] * scale + b0.x;
        s[j][1] = s[j][1] * scale + b0.y;
        s[j][2] = s[j][2] * scale + b1.x;
        s[j][3] = s[j][3] * scale + b1.y;
        mx0 = fmaxf(mx0, fmaxf(s[j][0], s[j][1]));
        mx1 = fmaxf(mx1, fmaxf(s[j][2], s[j][3]));
    }
    mx0 = fmaxf(mx0, __shfl_xor_sync(0xffffffffu, mx0, 1));
    mx0 = fmaxf(mx0, __shfl_xor_sync(0xffffffffu, mx0, 2));
    mx1 = fmaxf(mx1, __shfl_xor_sync(0xffffffffu, mx1, 1));
    mx1 = fmaxf(mx1, __shfl_xor_sync(0xffffffffu, mx1, 2));

    float sum0 = 0.f, sum1 = 0.f;
#pragma unroll
    for (int j = 0; j < 8; j++) {
        s[j][0] = __expf(s[j][0] - mx0);
        s[j][1] = __expf(s[j][1] - mx0);
        s[j][2] = __expf(s[j][2] - mx1);
        s[j][3] = __expf(s[j][3] - mx1);
        sum0 += s[j][0] + s[j][1];
        sum1 += s[j][2] + s[j][3];
    }
    sum0 += __shfl_xor_sync(0xffffffffu, sum0, 1);
    sum0 += __shfl_xor_sync(0xffffffffu, sum0, 2);
    sum1 += __shfl_xor_sync(0xffffffffu, sum1, 1);
    sum1 += __shfl_xor_sync(0xffffffffu, sum1, 2);
    const float inv0 = 1.0f / sum0, inv1 = 1.0f / sum1;

    // ---- P (fp16) over Q smem ----
    __syncwarp();
#pragma unroll
    for (int j = 0; j < 8; j++) {
        qp_s[(qr + g    ) * APITCH + j * 4 + tig] = pack2(s[j][0] * inv0, s[j][1] * inv0);
        qp_s[(qr + g + 8) * APITCH + j * 4 + tig] = pack2(s[j][2] * inv1, s[j][3] * inv1);
    }
    __syncwarp();

    // ---- O = P V ----
    float o[8][4];
#pragma unroll
    for (int j = 0; j < 8; j++)
#pragma unroll
        for (int c = 0; c < 4; c++) o[j][c] = 0.f;

#pragma unroll
    for (int kk = 0; kk < 4; kk++) {
        uint32_t a[4];
        ldm_x4(a, qp_base + (aq_off + (uint32_t)(kk * 8)) * 4u);
#pragma unroll
        for (int jj = 0; jj < 4; jj++) {
            uint32_t b[4];
            ldm_x4_trans(b, v_base + (bv_off + (uint32_t)(kk * 16 * APITCH + jj * 8)) * 4u);
            mma_f16(o[2 * jj    ], a, b[0], b[1]);
            mma_f16(o[2 * jj + 1], a, b[2], b[3]);
        }
    }

    // ---- output ----
    float* o0 = out + ((size_t)bw * 64 + qr + g) * 512 + h * 64;
    float* o1 = o0 + 8 * 512;
#pragma unroll
    for (int j = 0; j < 8; j++) {
        *(float2*)&o0[j * 8 + tig * 2] = make_float2(o[j][0], o[j][1]);
        *(float2*)&o1[j * 8 + tig * 2] = make_float2(o[j][2], o[j][3]);
    }
}

// ---------------------------------------------------------------------------
extern "C" void kernel_launch(void* const* d_in, const int* in_sizes, int n_in,
                              void* d_out, int out_size)
{
    const float* x  = (const float*)d_in[0];
    const float* Wq = (const float*)d_in[1];
    const float* bq = (const float*)d_in[2];
    const float* Wk = (const float*)d_in[3];
    const float* bk = (const float*)d_in[4];
    const float* Wv = (const float*)d_in[5];
    const float* bv = (const float*)d_in[6];
    const float* Bb = (const float*)d_in[7];
    float* out = (float*)d_out;

    cudaFuncSetAttribute(qkv_proj_kernel, cudaFuncAttributeMaxDynamicSharedMemorySize,
                         PROJ_SMEM);

    conv_x_kernel<<<8192, 256>>>(x);
    conv_w_kernel<<<384, 256>>>(Wq, Wk, Wv);

    dim3 gA(12, 256);
    qkv_proj_kernel<<<gA, 256, PROJ_SMEM>>>(bq, bk, bv);

    attn_kernel<<<4096, 128>>>(Bb, out);
}

// round 17
// speedup vs baseline: 1.1414x; 1.0071x over previous
#include <cuda_runtime.h>
#include <cuda_fp16.h>
#include <cstdint>

#define QKV_SZ (512u * 8u * 64u * 64u)   // halfs per matrix
__device__ __align__(16) __half g_qkv[3 * QKV_SZ];   // fp16 [which][bw][h][t][d]
__device__ __align__(16) __half g_xh[32768u * 512u]; // x as fp16
__device__ __align__(16) __half g_wh[1536u * 512u];  // Wq|Wk|Wv as fp16

__device__ __forceinline__ uint32_t pack2(float a, float b) {
    __half2 h = __halves2half2(__float2half_rn(a), __float2half_rn(b));
    return *(uint32_t*)&h;
}

__device__ __forceinline__ void mma_f16(float c[4], const uint32_t a[4],
                                        uint32_t b0, uint32_t b1) {
    asm volatile(
        "mma.sync.aligned.m16n8k16.row.col.f32.f16.f16.f32 "
        "{%0,%1,%2,%3}, {%4,%5,%6,%7}, {%8,%9}, {%0,%1,%2,%3};"
        : "+f"(c[0]), "+f"(c[1]), "+f"(c[2]), "+f"(c[3])
        : "r"(a[0]), "r"(a[1]), "r"(a[2]), "r"(a[3]), "r"(b0), "r"(b1));
}

__device__ __forceinline__ void ldm_x4(uint32_t* r, uint32_t addr) {
    asm volatile("ldmatrix.sync.aligned.m8n8.x4.shared.b16 {%0,%1,%2,%3}, [%4];"
                 : "=r"(r[0]), "=r"(r[1]), "=r"(r[2]), "=r"(r[3]) : "r"(addr));
}
__device__ __forceinline__ void ldm_x4_trans(uint32_t* r, uint32_t addr) {
    asm volatile("ldmatrix.sync.aligned.m8n8.x4.trans.shared.b16 {%0,%1,%2,%3}, [%4];"
                 : "=r"(r[0]), "=r"(r[1]), "=r"(r[2]), "=r"(r[3]) : "r"(addr));
}

__device__ __forceinline__ void cp_async16(uint32_t smem_addr, const void* gptr) {
    asm volatile("cp.async.cg.shared.global [%0], [%1], 16;\n" :: "r"(smem_addr), "l"(gptr));
}
__device__ __forceinline__ void cp_commit() { asm volatile("cp.async.commit_group;"); }
template <int N> __device__ __forceinline__ void cp_wait() {
    asm volatile("cp.async.wait_group %0;" :: "n"(N));
}

// ---------------------------------------------------------------------------
// Pre-convert: fp32 -> fp16(RN). 8 floats per thread.
// ---------------------------------------------------------------------------
__global__ void __launch_bounds__(256) conv_x_kernel(const float* __restrict__ x)
{
    const int i = blockIdx.x * 256 + threadIdx.x;
    float4 v0 = ((const float4*)x)[2 * i];
    float4 v1 = ((const float4*)x)[2 * i + 1];
    uint4 u;
    u.x = pack2(v0.x, v0.y); u.y = pack2(v0.z, v0.w);
    u.z = pack2(v1.x, v1.y); u.w = pack2(v1.z, v1.w);
    ((uint4*)g_xh)[i] = u;
}

__global__ void __launch_bounds__(256) conv_w_kernel(
    const float* __restrict__ Wq, const float* __restrict__ Wk, const float* __restrict__ Wv)
{
    const int i = blockIdx.x * 256 + threadIdx.x;
    const int which = i >> 15;
    const int sub = i & 32767;
    const float* W = (which == 0) ? Wq : (which == 1) ? Wk : Wv;
    float4 v0 = ((const float4*)W)[2 * sub];
    float4 v1 = ((const float4*)W)[2 * sub + 1];
    uint4 u;
    u.x = pack2(v0.x, v0.y); u.y = pack2(v0.z, v0.w);
    u.z = pack2(v1.x, v1.y); u.w = pack2(v1.z, v1.w);
    ((uint4*)g_wh)[i] = u;
}

// ---------------------------------------------------------------------------
// Kernel A: QKV projection, fp16 m16n8k16, 2 CTAs/SM.
// CTA tile 128x128, 128 threads, 4 warps of 64x64 (ldm:mma = 8:32 per step).
// K chunk 64, 3-stage cp.async pipeline. Fragment DOUBLE-BUFFERING: step s+1's
// 8 ldmatrix issued before step s's 32 mma -> crossbar hides under tensor.
// 256 threads/SM -> 256 regs/thread budget (acc 128 + dual frags 64 fits).
// Grid (12, 256): blockIdx.x = N-tile (fast) -> x L2 reuse.
// ---------------------------------------------------------------------------
#define KC 64
#define PW 36                            // words per staged row (32 data + 4 pad)
#define STAGE_W (256 * PW)               // 128 A rows + 128 B rows = 9216 words
#define NSTAGE 3
#define PROJ_SMEM (NSTAGE * STAGE_W * 4) // 110592 B -> 2 CTAs/SM

__global__ void __launch_bounds__(128, 2) qkv_proj_kernel(
    const float* __restrict__ bq, const float* __restrict__ bk, const float* __restrict__ bv)
{
    extern __shared__ uint32_t sm[];

    const int tid  = threadIdx.x;
    const int warp = tid >> 5, lane = tid & 31;
    const int g = lane >> 2, tig = lane & 3;
    const int l8 = lane >> 3, r8 = lane & 7;
    const int wm = (warp >> 1) * 64;     // 2x2 grid of 64x64 warp tiles
    const int wn = (warp & 1) * 64;

    const int nb = blockIdx.x * 128;
    const int mb = blockIdx.y * 128;
    const int which = nb >> 9;
    const int nw0 = nb & 511;
    const float* __restrict__ bias = (which == 0) ? bq : (which == 1) ? bk : bv;
    __half* __restrict__ dst = g_qkv + (size_t)which * QKV_SZ;

    const uint32_t smem_base = (uint32_t)__cvta_generic_to_shared(sm);

    // A frag i: rows wm+i*16 + {0-7,8-15}, k halves k0/k8
    const uint32_t a_off = (uint32_t)((wm + (l8 & 1) * 8 + r8) * PW + (l8 >> 1) * 4);
    // B frag jj: rows 128 + wn + jj*16 + n-octet; (n0-7,k0)(n0-7,k8)(n8-15,k0)(n8-15,k8)
    const uint32_t b_off = (uint32_t)((128 + wn + (l8 >> 1) * 8 + r8) * PW + (l8 & 1) * 4);

    float acc[4][8][4];
#pragma unroll
    for (int i = 0; i < 4; i++)
#pragma unroll
        for (int j = 0; j < 8; j++)
#pragma unroll
            for (int c = 0; c < 4; c++) acc[i][j][c] = 0.f;

    // Per stage: (128 A + 128 B) rows x 8 x 16B = 2048 cp ops, 16/thread.
    auto issue = [&](int c) {
        const uint32_t sbase = smem_base + (uint32_t)((c % NSTAGE) * STAGE_W) * 4u;
        const int kel = c * KC;
#pragma unroll
        for (int q = 0; q < 16; q++) {
            const int idx = q * 128 + tid;
            if (idx < 1024) {            // A
                const int row = idx >> 3, seg = idx & 7;
                cp_async16(sbase + (uint32_t)(row * PW + seg * 4) * 4u,
                           g_xh + (size_t)(mb + row) * 512 + kel + seg * 8);
            } else {                     // B
                const int bidx = idx - 1024;
                const int row = bidx >> 3, seg = bidx & 7;
                cp_async16(sbase + (uint32_t)((128 + row) * PW + seg * 4) * 4u,
                           g_wh + (size_t)(nb + row) * 512 + kel + seg * 8);
            }
        }
        cp_commit();
    };

    issue(0); issue(1);

    uint32_t aF[2][4][4], bF[2][4][4];

    auto ldm_step = [&](uint32_t stage_addr, int step, int buf) {
        const uint32_t so = stage_addr + (uint32_t)(step * 8) * 4u;
#pragma unroll
        for (int i = 0; i < 4; i++)
            ldm_x4(aF[buf][i], so + (a_off + (uint32_t)(i * 16 * PW)) * 4u);
#pragma unroll
        for (int jj = 0; jj < 4; jj++)
            ldm_x4(bF[buf][jj], so + (b_off + (uint32_t)(jj * 16 * PW)) * 4u);
    };
    auto mma_step = [&](int buf) {
#pragma unroll
        for (int jj = 0; jj < 4; jj++)
#pragma unroll
            for (int i = 0; i < 4; i++) {
                mma_f16(acc[i][2 * jj    ], aF[buf][i], bF[buf][jj][0], bF[buf][jj][1]);
                mma_f16(acc[i][2 * jj + 1], aF[buf][i], bF[buf][jj][2], bF[buf][jj][3]);
            }
    };

    for (int c = 0; c < 8; c++) {
        if (c < 7) cp_wait<1>(); else cp_wait<0>();
        __syncthreads();
        if (c + 2 < 8) issue(c + 2);

        const uint32_t stage_addr = smem_base + (uint32_t)((c % NSTAGE) * STAGE_W) * 4u;

        ldm_step(stage_addr, 0, 0);
#pragma unroll
        for (int step = 0; step < 4; step++) {
            if (step < 3) ldm_step(stage_addr, step + 1, (step + 1) & 1);
            mma_step(step & 1);
        }
    }

    // Epilogue: +bias fp32, pack half2, scatter [bw][h][t][d].
#pragma unroll
    for (int i = 0; i < 4; i++) {
        const int m0 = mb + wm + i * 16 + g;
#pragma unroll
        for (int j = 0; j < 8; j++) {
            const int col = nw0 + wn + j * 8 + tig * 2;
            const float bv0 = bias[col], bv1 = bias[col + 1];
            const int h = col >> 6, d = col & 63;
            {
                const int m = m0;
                size_t o = (((size_t)(m >> 6) * 8 + h) * 64 + (m & 63)) * 64 + d;
                *(uint32_t*)&dst[o] = pack2(acc[i][j][0] + bv0, acc[i][j][1] + bv1);
            }
            {
                const int m = m0 + 8;
                size_t o = (((size_t)(m >> 6) * 8 + h) * 64 + (m & 63)) * 64 + d;
                *(uint32_t*)&dst[o] = pack2(acc[i][j][2] + bv0, acc[i][j][3] + bv1);
            }
        }
    }
}

// ---------------------------------------------------------------------------
// Kernel B: per-(window, head) attention, fp16 mma + ldmatrix.x4.
// 4096 CTAs x 128 threads. Q/K/V via cp.async (12 x 16B in flight / thread).
// ---------------------------------------------------------------------------
#define APITCH 36

__global__ void __launch_bounds__(128) attn_kernel(
    const float* __restrict__ Bbias, float* __restrict__ out)
{
    __shared__ uint32_t qp_s[64 * APITCH];   // Q, later P (warp-private rows)
    __shared__ uint32_t k_s [64 * APITCH];
    __shared__ uint32_t v_s [64 * APITCH];   // [t][d] row-major

    const int tid  = threadIdx.x;
    const int warp = tid >> 5, lane = tid & 31;
    const int g = lane >> 2, tig = lane & 3;
    const int l8 = lane >> 3, r8 = lane & 7;
    const int wh = blockIdx.x;
    const int h  = wh & 7;
    const int bw = wh >> 3;
    const size_t base = (size_t)wh * 4096;

    const __half* qg = g_qkv + base;
    const __half* kg = g_qkv + QKV_SZ + base;
    const __half* vg = g_qkv + 2u * QKV_SZ + base;

    const uint32_t qp_base = (uint32_t)__cvta_generic_to_shared(qp_s);
    const uint32_t k_base  = (uint32_t)__cvta_generic_to_shared(k_s);
    const uint32_t v_base  = (uint32_t)__cvta_generic_to_shared(v_s);

#pragma unroll
    for (int i = 0; i < 4; i++) {
        const int c = i * 128 + tid;
        const int t = c >> 3, w4 = (c & 7) * 4;
        const uint32_t soff = (uint32_t)(t * APITCH + w4) * 4u;
        cp_async16(qp_base + soff, qg + c * 8);
        cp_async16(k_base  + soff, kg + c * 8);
        cp_async16(v_base  + soff, vg + c * 8);
    }
    cp_commit();
    cp_wait<0>();
    __syncthreads();

    const int qr = warp * 16;

    const uint32_t aq_off = (uint32_t)((qr + (l8 & 1) * 8 + r8) * APITCH + (l8 >> 1) * 4);
    const uint32_t bk_off = (uint32_t)(((l8 >> 1) * 8 + r8) * APITCH + (l8 & 1) * 4);
    const uint32_t bv_off = (uint32_t)(((l8 & 1) * 8 + r8) * APITCH + (l8 >> 1) * 4);

    // ---- S = Q K^T ----
    float s[8][4];
#pragma unroll
    for (int j = 0; j < 8; j++)
#pragma unroll
        for (int c = 0; c < 4; c++) s[j][c] = 0.f;

#pragma unroll
    for (int kk = 0; kk < 4; kk++) {
        uint32_t a[4];
        ldm_x4(a, qp_base + (aq_off + (uint32_t)(kk * 8)) * 4u);
#pragma unroll
        for (int jj = 0; jj < 4; jj++) {
            uint32_t b[4];
            ldm_x4(b, k_base + (bk_off + (uint32_t)(jj * 16 * APITCH + kk * 8)) * 4u);
            mma_f16(s[2 * jj    ], a, b[0], b[1]);
            mma_f16(s[2 * jj + 1], a, b[2], b[3]);
        }
    }

    // ---- scale + bias + softmax ----
    const float scale = 0.125f;
    float mx0 = -1e30f, mx1 = -1e30f;
#pragma unroll
    for (int j = 0; j < 8; j++) {
        float2 b0 = *(const float2*)&Bbias[(qr + g    ) * 64 + j * 8 + tig * 2];
        float2 b1 = *(const float2*)&Bbias[(qr + g + 8) * 64 + j * 8 + tig * 2];
        s[j][0] = s[j][0] * scale + b0.x;
        s[j][1] = s[j][1] * scale + b0.y;
        s[j][2] = s[j][2] * scale + b1.x;
        s[j][3] = s[j][3] * scale + b1.y;
        mx0 = fmaxf(mx0, fmaxf(s[j][0], s[j][1]));
        mx1 = fmaxf(mx1, fmaxf(s[j][2], s[j][3]));
    }
    mx0 = fmaxf(mx0, __shfl_xor_sync(0xffffffffu, mx0, 1));
    mx0 = fmaxf(mx0, __shfl_xor_sync(0xffffffffu, mx0, 2));
    mx1 = fmaxf(mx1, __shfl_xor_sync(0xffffffffu, mx1, 1));
    mx1 = fmaxf(mx1, __shfl_xor_sync(0xffffffffu, mx1, 2));

    float sum0 = 0.f, sum1 = 0.f;
#pragma unroll
    for (int j = 0; j < 8; j++) {
        s[j][0] = __expf(s[j][0] - mx0);
        s[j][1] = __expf(s[j][1] - mx0);
        s[j][2] = __expf(s[j][2] - mx1);
        s[j][3] = __expf(s[j][3] - mx1);
        sum0 += s[j][0] + s[j][1];
        sum1 += s[j][2] + s[j][3];
    }
    sum0 += __shfl_xor_sync(0xffffffffu, sum0, 1);
    sum0 += __shfl_xor_sync(0xffffffffu, sum0, 2);
    sum1 += __shfl_xor_sync(0xffffffffu, sum1, 1);
    sum1 += __shfl_xor_sync(0xffffffffu, sum1, 2);
    const float inv0 = 1.0f / sum0, inv1 = 1.0f / sum1;

    // ---- P (fp16) over Q smem ----
    __syncwarp();
#pragma unroll
    for (int j = 0; j < 8; j++) {
        qp_s[(qr + g    ) * APITCH + j * 4 + tig] = pack2(s[j][0] * inv0, s[j][1] * inv0);
        qp_s[(qr + g + 8) * APITCH + j * 4 + tig] = pack2(s[j][2] * inv1, s[j][3] * inv1);
    }
    __syncwarp();

    // ---- O = P V ----
    float o[8][4];
#pragma unroll
    for (int j = 0; j < 8; j++)
#pragma unroll
        for (int c = 0; c < 4; c++) o[j][c] = 0.f;

#pragma unroll
    for (int kk = 0; kk < 4; kk++) {
        uint32_t a[4];
        ldm_x4(a, qp_base + (aq_off + (uint32_t)(kk * 8)) * 4u);
#pragma unroll
        for (int jj = 0; jj < 4; jj++) {
            uint32_t b[4];
            ldm_x4_trans(b, v_base + (bv_off + (uint32_t)(kk * 16 * APITCH + jj * 8)) * 4u);
            mma_f16(o[2 * jj    ], a, b[0], b[1]);
            mma_f16(o[2 * jj + 1], a, b[2], b[3]);
        }
    }

    // ---- output ----
    float* o0 = out + ((size_t)bw * 64 + qr + g) * 512 + h * 64;
    float* o1 = o0 + 8 * 512;
#pragma unroll
    for (int j = 0; j < 8; j++) {
        *(float2*)&o0[j * 8 + tig * 2] = make_float2(o[j][0], o[j][1]);
        *(float2*)&o1[j * 8 + tig * 2] = make_float2(o[j][2], o[j][3]);
    }
}

// ---------------------------------------------------------------------------
extern "C" void kernel_launch(void* const* d_in, const int* in_sizes, int n_in,
                              void* d_out, int out_size)
{
    const float* x  = (const float*)d_in[0];
    const float* Wq = (const float*)d_in[1];
    const float* bq = (const float*)d_in[2];
    const float* Wk = (const float*)d_in[3];
    const float* bk = (const float*)d_in[4];
    const float* Wv = (const float*)d_in[5];
    const float* bv = (const float*)d_in[6];
    const float* Bb = (const float*)d_in[7];
    float* out = (float*)d_out;

    cudaFuncSetAttribute(qkv_proj_kernel, cudaFuncAttributeMaxDynamicSharedMemorySize,
                         PROJ_SMEM);

    conv_x_kernel<<<8192, 256>>>(x);
    conv_w_kernel<<<384, 256>>>(Wq, Wk, Wv);

    dim3 gA(12, 256);
    qkv_proj_kernel<<<gA, 128, PROJ_SMEM>>>(bq, bk, bv);

    attn_kernel<<<4096, 128>>>(Bb, out);
}